// round 5
// baseline (speedup 1.0000x reference)
#include <cuda_runtime.h>
#include <cuda_fp16.h>
#include <cstdint>

#define BMAX 16384
__device__ float g_xp[BMAX * 512];
__device__ float g_hs[BMAX * 128];
__device__ float g_c2wt[32 * 9 * 64];   // conv2 weights [ic][k][oc]
__device__ float g_d1wt[64 * 9 * 32];   // deconv1 conv-equiv weights [ic][k][oc] (flip folded)

__device__ __forceinline__ float fsig(float x) { return 1.0f / (1.0f + __expf(-x)); }
__device__ __forceinline__ float ftanh(float x) { return 2.0f * fsig(2.0f * x) - 1.0f; }
__device__ __forceinline__ unsigned pack2(float x, float y) {
    __half2 h = __floats2half2_rn(x, y);
    return *reinterpret_cast<unsigned*>(&h);
}
__device__ __forceinline__ void mma16816(float* c, const unsigned* a, unsigned b0, unsigned b1) {
    asm volatile(
        "mma.sync.aligned.m16n8k16.row.col.f32.f16.f16.f32 "
        "{%0,%1,%2,%3},{%4,%5,%6,%7},{%8,%9},{%0,%1,%2,%3};\n"
        : "+f"(c[0]), "+f"(c[1]), "+f"(c[2]), "+f"(c[3])
        : "r"(a[0]), "r"(a[1]), "r"(a[2]), "r"(a[3]), "r"(b0), "r"(b1));
}
// packed f32x2 fma: acc += a*b (two lanes)
__device__ __forceinline__ void fma2(unsigned long long& acc, unsigned long long a, unsigned long long b) {
    asm("fma.rn.f32x2 %0, %1, %2, %0;" : "+l"(acc) : "l"(a), "l"(b));
}
__device__ __forceinline__ unsigned long long pk2(float x) {
    unsigned long long r; asm("mov.b64 %0, {%1,%2};" : "=l"(r) : "f"(x), "f"(x)); return r;
}
__device__ __forceinline__ float2 upk2(unsigned long long v) {
    float2 r; asm("mov.b64 {%0,%1}, %2;" : "=f"(r.x), "=f"(r.y) : "l"(v)); return r;
}
__device__ __forceinline__ void cp_async8(uint32_t s, const void* g) {
    asm volatile("cp.async.ca.shared.global [%0], [%1], 8;" :: "r"(s), "l"(g));
}
__device__ __forceinline__ void cp_commit() { asm volatile("cp.async.commit_group;"); }
__device__ __forceinline__ void cp_wait5() { asm volatile("cp.async.wait_group 5;"); }

// ================= weight prep =================
__global__ void prep_kernel(const float* __restrict__ c2w, const float* __restrict__ d1w) {
    int i = blockIdx.x * 256 + threadIdx.x;
    if (i < 18432) {
        // c2w[(oc*32+ic)*9+k] -> g_c2wt[(ic*9+k)*64+oc]
        int oc = i / 288, r = i % 288, ic = r / 9, k = r % 9;
        g_c2wt[(ic * 9 + k) * 64 + oc] = c2w[i];
        // d1w[(ic*32+oc)*9+kk] -> g_d1wt[(ic*9+(8-kk))*32+oc]
        int ic2 = i / 288, r2 = i % 288, oc2 = r2 / 9, kk = r2 % 9;
        g_d1wt[(ic2 * 9 + (8 - kk)) * 32 + oc2] = d1w[i];
    }
}

// ================= encoder + input projection =================
__global__ void __launch_bounds__(128) enc_kernel(
    const float* __restrict__ img, const float* __restrict__ act,
    const float* __restrict__ c1w, const float* __restrict__ c1b,
    const float* __restrict__ c2b,
    const float* __restrict__ encw, const float* __restrict__ encb,
    const float* __restrict__ wih, const float* __restrict__ bih,
    const float* __restrict__ bhh, int B)
{
    __shared__ float s_img[4][76];
    __shared__ float s_x[4][136];
    __shared__ float s_h2[4][1600];
    __shared__ float s_wt[4608];      // region: h1 (4x800) / weight tiles

    int tid = threadIdx.x, lane = tid & 31, w = tid >> 5;
    int gi = blockIdx.x * 4 + w;
    bool valid = gi < B;
    float* s_h1 = s_wt + w * 800;

    if (valid) {
        for (int i = lane; i < 75; i += 32) s_img[w][i] = img[gi * 75 + i];
        if (lane < 8) s_x[w][128 + lane] = act[gi * 8 + lane];
    }
    __syncwarp();

    int pidx[9];
    {
        int y = (lane < 25) ? lane / 5 : 0, x = (lane < 25) ? lane % 5 : 0;
        #pragma unroll
        for (int ky = 0; ky < 3; ky++)
            #pragma unroll
            for (int kx = 0; kx < 3; kx++) {
                int yy = y + ky - 1, xx = x + kx - 1;
                pidx[ky*3+kx] = (yy >= 0 && yy < 5 && xx >= 0 && xx < 5) ? yy*5+xx : -1;
            }
    }

    // ---- conv1 (3->32) relu ----
    if (lane < 25) {
        float p1[27];
        #pragma unroll
        for (int ic = 0; ic < 3; ic++)
            #pragma unroll
            for (int j = 0; j < 9; j++)
                p1[ic*9+j] = (pidx[j] >= 0) ? s_img[w][ic*25 + pidx[j]] : 0.f;
        #pragma unroll 4
        for (int oc = 0; oc < 32; oc++) {
            float a = __ldg(&c1b[oc]);
            #pragma unroll
            for (int k = 0; k < 27; k++) a += p1[k] * __ldg(&c1w[oc*27+k]);
            s_h1[oc*25+lane] = fmaxf(a, 0.f);
        }
    }
    __syncwarp();

    // ---- conv2 (32->64) relu : f32x2 + vector weight loads ----
    if (lane < 25) {
        unsigned long long acc2[32];
        #pragma unroll
        for (int q = 0; q < 32; q++) acc2[q] = 0ull;
        for (int ic = 0; ic < 32; ic++) {
            const float* hp = s_h1 + ic * 25;
            unsigned long long p2[9];
            #pragma unroll
            for (int j = 0; j < 9; j++)
                p2[j] = pk2((pidx[j] >= 0) ? hp[pidx[j]] : 0.f);
            const ulonglong2* wt = reinterpret_cast<const ulonglong2*>(&g_c2wt[ic * 576]);
            #pragma unroll
            for (int k = 0; k < 9; k++) {
                #pragma unroll
                for (int q = 0; q < 16; q++) {
                    ulonglong2 wv = __ldg(&wt[k*16 + q]);
                    fma2(acc2[q*2],   p2[k], wv.x);
                    fma2(acc2[q*2+1], p2[k], wv.y);
                }
            }
        }
        #pragma unroll
        for (int q = 0; q < 32; q++) {
            float2 v = upk2(acc2[q]);
            s_h2[w][(2*q)*25   + lane] = fmaxf(v.x + __ldg(&c2b[2*q]),   0.f);
            s_h2[w][(2*q+1)*25 + lane] = fmaxf(v.y + __ldg(&c2b[2*q+1]), 0.f);
        }
    }
    __syncthreads();   // h1 region reusable as tile buffer

    // ---- enc linear: z = h2 @ enc_w^T + enc_b (tiled, pitch 132) ----
    for (int ot = 0; ot < 4; ot++) {
        float acc = 0.f;
        for (int kt = 0; kt < 13; kt++) {
            int k0 = kt * 128, klen = (kt == 12) ? 64 : 128;
            __syncthreads();
            for (int idx = tid; idx < 32 * klen; idx += 128) {
                int r = idx / klen, k = idx - r * klen;
                s_wt[r*132 + k] = encw[(ot*32 + r)*1600 + k0 + k];
            }
            __syncthreads();
            const float4* wt4 = reinterpret_cast<const float4*>(&s_wt[lane*132]);
            const float4* h4  = reinterpret_cast<const float4*>(&s_h2[w][k0]);
            int n4 = klen >> 2;
            #pragma unroll 8
            for (int q = 0; q < n4; q++) {
                float4 wv = wt4[q], hv = h4[q];
                acc += wv.x*hv.x + wv.y*hv.y + wv.z*hv.z + wv.w*hv.w;
            }
        }
        s_x[w][ot*32 + lane] = acc + __ldg(&encb[ot*32 + lane]);
    }

    // ---- xp = [z,action] @ w_ih^T + (b_ih+b_hh) (tiled, pitch 144) ----
    for (int ot = 0; ot < 16; ot++) {
        __syncthreads();
        for (int idx = tid; idx < 32 * 136; idx += 128) {
            int r = idx / 136, k = idx - r * 136;
            s_wt[r*144 + k] = wih[(ot*32 + r)*136 + k];
        }
        __syncthreads();
        float acc = 0.f;
        const float4* wt4 = reinterpret_cast<const float4*>(&s_wt[lane*144]);
        const float4* xv4 = reinterpret_cast<const float4*>(&s_x[w][0]);
        #pragma unroll 17
        for (int q = 0; q < 34; q++) {
            float4 wv = wt4[q], xv = xv4[q];
            acc += wv.x*xv.x + wv.y*xv.y + wv.z*xv.z + wv.w*xv.w;
        }
        if (valid) {
            int o = ot*32 + lane;
            g_xp[gi*512 + o] = acc + __ldg(&bih[o]) + __ldg(&bhh[o]);
        }
    }
}

// ================= LSTM: 1 block, 8 warps, 4 gate-tiles/warp =================
// warp w owns gates i,f,g,o (tiles g*8+w) for h rows [16w,16w+16).
// One __syncthreads/step. xp via cp.async ring (depth 8, distance 6).
__global__ void __launch_bounds__(256) lstm_kernel(
    const float* __restrict__ whh, float* __restrict__ d_out, int B, int out_size)
{
    __shared__ unsigned hbuf[2][64];
    __shared__ float s_xp[8][512];

    int tid = threadIdx.x, lane = tid & 31, w = tid >> 5;
    int gr = lane >> 2, tg = lane & 3;

    // W_hh fragments: a[gate][kt][4]
    unsigned a[4][8][4];
    #pragma unroll
    for (int g = 0; g < 4; g++) {
        int m0 = (g*8 + w) * 16;
        #pragma unroll
        for (int kt = 0; kt < 8; kt++) {
            int k0 = kt*16, r0 = m0+gr, r1 = m0+8+gr, c0 = k0+tg*2, c1 = c0+8;
            a[g][kt][0] = pack2(__ldg(&whh[r0*128+c0]), __ldg(&whh[r0*128+c0+1]));
            a[g][kt][1] = pack2(__ldg(&whh[r1*128+c0]), __ldg(&whh[r1*128+c0+1]));
            a[g][kt][2] = pack2(__ldg(&whh[r0*128+c1]), __ldg(&whh[r0*128+c1+1]));
            a[g][kt][3] = pack2(__ldg(&whh[r1*128+c1]), __ldg(&whh[r1*128+c1+1]));
        }
    }
    int r0 = w*16 + gr, r1 = r0 + 8;          // h rows produced (at tg==0)
    int xA = (tg*8 + w)*16 + gr, xB = xA + 8; // xp rows for this lane's gate
    if (tid < 64) hbuf[0][tid] = 0u;

    // prefill xp ring: groups for steps 0..5
    #pragma unroll
    for (int d = 0; d < 6; d++) {
        if (d < B) {
            uint32_t s = (uint32_t)__cvta_generic_to_shared(&s_xp[d][2*tid]);
            cp_async8(s, &g_xp[d*512 + 2*tid]);
        }
        cp_commit();
    }
    cp_wait5();
    __syncthreads();

    float cA = 0.f, cB = 0.f;
    for (int t = 0; t < B; t++) {
        const unsigned* h2p = hbuf[t & 1];
        float aE[4][4], aO[4][4];
        #pragma unroll
        for (int g = 0; g < 4; g++)
            #pragma unroll
            for (int j = 0; j < 4; j++) { aE[g][j] = 0.f; aO[g][j] = 0.f; }
        #pragma unroll
        for (int kt = 0; kt < 8; kt += 2) {
            unsigned b0 = h2p[kt*8 + tg],     b1 = h2p[kt*8 + 4 + tg];
            unsigned d0 = h2p[(kt+1)*8 + tg], d1 = h2p[(kt+1)*8 + 4 + tg];
            #pragma unroll
            for (int g = 0; g < 4; g++) {
                mma16816(aE[g], a[g][kt],   b0, b1);
                mma16816(aO[g], a[g][kt+1], d0, d1);
            }
        }
        // distribute: lane tg handles gate tg (rows r0,r1) — shuffle from tg0 lane
        int src = lane & ~3;
        float sA[4], sB[4];
        #pragma unroll
        for (int g = 0; g < 4; g++) {
            sA[g] = __shfl_sync(0xffffffffu, aE[g][0] + aO[g][0], src);
            sB[g] = __shfl_sync(0xffffffffu, aE[g][2] + aO[g][2], src);
        }
        int slot = t & 7;
        float preA = ((tg==0) ? sA[0] : (tg==1) ? sA[1] : (tg==2) ? sA[2] : sA[3]) + s_xp[slot][xA];
        float preB = ((tg==0) ? sB[0] : (tg==1) ? sB[1] : (tg==2) ? sB[2] : sB[3]) + s_xp[slot][xB];
        bool isg = (tg == 2);
        float zA = isg ? 2.f*preA : preA;
        float zB = isg ? 2.f*preB : preB;
        float vA = fsig(zA), vB = fsig(zB);
        float actA = isg ? fmaf(2.f, vA, -1.f) : vA;   // tg2: tanh(g)
        float actB = isg ? fmaf(2.f, vB, -1.f) : vB;
        // gather f,g,o to tg0
        int b = lane & ~3;
        float fA = __shfl_sync(0xffffffffu, actA, b|1);
        float gA = __shfl_sync(0xffffffffu, actA, b|2);
        float oA = __shfl_sync(0xffffffffu, actA, b|3);
        float fB = __shfl_sync(0xffffffffu, actB, b|1);
        float gB = __shfl_sync(0xffffffffu, actB, b|2);
        float oB = __shfl_sync(0xffffffffu, actB, b|3);
        if (tg == 0) {
            cA = fmaf(fA, cA, actA * gA);
            cB = fmaf(fB, cB, actB * gB);
            float hA = oA * ftanh(cA);
            float hB = oB * ftanh(cB);
            __half* hn = reinterpret_cast<__half*>(hbuf[(t+1) & 1]);
            hn[r0] = __float2half_rn(hA);
            hn[r1] = __float2half_rn(hB);
            g_hs[t*128 + r0] = hA;
            g_hs[t*128 + r1] = hB;
            if (t == B - 1) {
                d_out[out_size - 256 + r0] = hA;
                d_out[out_size - 256 + r1] = hB;
                d_out[out_size - 128 + r0] = cA;
                d_out[out_size - 128 + r1] = cB;
            }
        }
        // prefetch xp for step t+6
        int tf = t + 6;
        if (tf < B) {
            uint32_t s = (uint32_t)__cvta_generic_to_shared(&s_xp[tf & 7][2*tid]);
            cp_async8(s, &g_xp[tf*512 + 2*tid]);
        }
        cp_commit();
        cp_wait5();
        __syncthreads();
    }
}

// ================= decoder =================
__global__ void __launch_bounds__(128) dec_kernel(
    const float* __restrict__ decw, const float* __restrict__ decb,
    const float* __restrict__ d1b,
    const float* __restrict__ d2w, const float* __restrict__ d2b,
    float* __restrict__ out, int B)
{
    __shared__ float s_hs[4][128];
    __shared__ float s_d[4][1600];
    __shared__ float s_wt[4224];     // region: weight tiles / deconv1 output (4x800)
    __shared__ float s_w2f[864];

    int tid = threadIdx.x, lane = tid & 31, w = tid >> 5;
    int gi = blockIdx.x * 4 + w;
    bool valid = gi < B;

    for (int i = tid; i < 864; i += 128) {
        int ic = i / 27, rem = i % 27, oc = rem / 9, k = rem % 9;
        s_w2f[i] = d2w[(ic*3 + oc)*9 + (8 - k)];
    }
    if (valid)
        for (int i = lane; i < 128; i += 32) s_hs[w][i] = g_hs[gi*128 + i];

    // ---- dec linear (tiled, pitch 132) ----
    for (int ot = 0; ot < 50; ot++) {
        __syncthreads();
        for (int idx = tid; idx < 4096; idx += 128) {
            int r = idx >> 7, k = idx & 127;
            s_wt[r*132 + k] = decw[(ot*32 + r)*128 + k];
        }
        __syncthreads();
        float acc = 0.f;
        const float4* wt4 = reinterpret_cast<const float4*>(&s_wt[lane*132]);
        const float4* h4  = reinterpret_cast<const float4*>(&s_hs[w][0]);
        #pragma unroll 8
        for (int q = 0; q < 32; q++) {
            float4 wv = wt4[q], hv = h4[q];
            acc += wv.x*hv.x + wv.y*hv.y + wv.z*hv.z + wv.w*hv.w;
        }
        s_d[w][ot*32 + lane] = acc + __ldg(&decb[ot*32 + lane]);
    }
    __syncthreads();

    float* s_h1 = s_wt + w * 800;
    int pidx[9];
    {
        int y = (lane < 25) ? lane / 5 : 0, x = (lane < 25) ? lane % 5 : 0;
        #pragma unroll
        for (int ky = 0; ky < 3; ky++)
            #pragma unroll
            for (int kx = 0; kx < 3; kx++) {
                int yy = y + ky - 1, xx = x + kx - 1;
                pidx[ky*3+kx] = (yy >= 0 && yy < 5 && xx >= 0 && xx < 5) ? yy*5+xx : -1;
            }
    }

    // ---- deconv1 (64->32) relu : f32x2 + vector weight loads ----
    if (lane < 25) {
        unsigned long long acc2[16];
        #pragma unroll
        for (int q = 0; q < 16; q++) acc2[q] = 0ull;
        for (int ic = 0; ic < 64; ic++) {
            const float* dp = &s_d[w][ic * 25];
            unsigned long long p2[9];
            #pragma unroll
            for (int j = 0; j < 9; j++)
                p2[j] = pk2((pidx[j] >= 0) ? dp[pidx[j]] : 0.f);
            const ulonglong2* wt = reinterpret_cast<const ulonglong2*>(&g_d1wt[ic * 288]);
            #pragma unroll
            for (int k = 0; k < 9; k++) {
                #pragma unroll
                for (int q = 0; q < 8; q++) {
                    ulonglong2 wv = __ldg(&wt[k*8 + q]);
                    fma2(acc2[q*2],   p2[k], wv.x);
                    fma2(acc2[q*2+1], p2[k], wv.y);
                }
            }
        }
        #pragma unroll
        for (int q = 0; q < 16; q++) {
            float2 v = upk2(acc2[q]);
            s_h1[(2*q)*25   + lane] = fmaxf(v.x + __ldg(&d1b[2*q]),   0.f);
            s_h1[(2*q+1)*25 + lane] = fmaxf(v.y + __ldg(&d1b[2*q+1]), 0.f);
        }
    }
    __syncwarp();

    // ---- deconv2 (32->3) sigmoid ----
    if (valid && lane < 25) {
        float acc[3] = {__ldg(&d2b[0]), __ldg(&d2b[1]), __ldg(&d2b[2])};
        for (int ic = 0; ic < 32; ic++) {
            float p[9];
            #pragma unroll
            for (int j = 0; j < 9; j++)
                p[j] = (pidx[j] >= 0) ? s_h1[ic*25 + pidx[j]] : 0.f;
            #pragma unroll
            for (int oc = 0; oc < 3; oc++) {
                float a = acc[oc];
                #pragma unroll
                for (int k = 0; k < 9; k++) a += p[k] * s_w2f[ic*27 + oc*9 + k];
                acc[oc] = a;
            }
        }
        #pragma unroll
        for (int oc = 0; oc < 3; oc++)
            out[gi*75 + oc*25 + lane] = fsig(acc[oc]);
    }
}

extern "C" void kernel_launch(void* const* d_in, const int* in_sizes, int n_in,
                              void* d_out, int out_size)
{
    const float* img   = (const float*)d_in[0];
    const float* act   = (const float*)d_in[1];
    const float* c1w   = (const float*)d_in[2];
    const float* c1b   = (const float*)d_in[3];
    const float* c2w   = (const float*)d_in[4];
    const float* c2b   = (const float*)d_in[5];
    const float* encw  = (const float*)d_in[6];
    const float* encb  = (const float*)d_in[7];
    const float* wih   = (const float*)d_in[8];
    const float* whh   = (const float*)d_in[9];
    const float* bih   = (const float*)d_in[10];
    const float* bhh   = (const float*)d_in[11];
    const float* decw  = (const float*)d_in[12];
    const float* decb  = (const float*)d_in[13];
    const float* d1w   = (const float*)d_in[14];
    const float* d1b   = (const float*)d_in[15];
    const float* d2w   = (const float*)d_in[16];
    const float* d2b   = (const float*)d_in[17];
    float* out = (float*)d_out;

    int B = in_sizes[0] / 75;
    int blocks = (B + 3) / 4;

    prep_kernel<<<72, 256>>>(c2w, d1w);
    enc_kernel<<<blocks, 128>>>(img, act, c1w, c1b, c2b, encw, encb, wih, bih, bhh, B);
    lstm_kernel<<<1, 256>>>(whh, out, B, out_size);
    dec_kernel<<<blocks, 128>>>(decw, decb, d1b, d2w, d2b, out, B);
}